// round 1
// baseline (speedup 1.0000x reference)
#include <cuda_runtime.h>
#include <cuda_bf16.h>

// ---------------------------------------------------------------------------
// MoE layer: B=4,S=2048,D=1024,E=8,F=4096, top-k=2
// Sparse routing: gate -> permute tokens by expert (128-padded segments) ->
// per-expert GEMM1(+gelu) -> GEMM2 -> weighted combine.
// ---------------------------------------------------------------------------

#define T_TOK   8192          // B*S
#define DDIM    1024
#define EEXP    8
#define FDIM    4096
#define NASSIGN (T_TOK * 2)   // 16384
#define SEGPAD  128
#define MAXSLOTS (NASSIGN + EEXP * SEGPAD)  // 17408

// ---- device-global scratch (no dynamic allocation allowed) ----
__device__ float g_xp[MAXSLOTS * (size_t)DDIM];   // permuted inputs
__device__ float g_h [MAXSLOTS * (size_t)FDIM];   // hidden activations
__device__ float g_y [MAXSLOTS * (size_t)DDIM];   // expert outputs
__device__ int   g_te[NASSIGN];                   // expert id per assignment
__device__ float g_tw[NASSIGN];                   // gate weight per assignment
__device__ int   g_slot[NASSIGN];                 // slot per assignment
__device__ int   g_count[EEXP];
__device__ int   g_cursor[EEXP];
__device__ int   g_offs[EEXP + 1];                // padded segment offsets

// ---------------------------------------------------------------------------
__global__ void k_init() {
    int i = threadIdx.x;
    if (i < EEXP) { g_count[i] = 0; g_cursor[i] = 0; }
}

// Gate: logits = x @ Wg, stable top-2, softmax over top-2.
__global__ void k_gate(const float* __restrict__ x, const float* __restrict__ Wg) {
    int t = blockIdx.x;
    int tid = threadIdx.x;
    const float* xr = x + (size_t)t * DDIM;

    float acc[EEXP];
#pragma unroll
    for (int e = 0; e < EEXP; e++) acc[e] = 0.f;

    for (int d = tid; d < DDIM; d += 256) {
        float xv = xr[d];
        const float* wr = Wg + (size_t)d * EEXP;
#pragma unroll
        for (int e = 0; e < EEXP; e++) acc[e] += xv * wr[e];
    }

    __shared__ float red[256][EEXP];
#pragma unroll
    for (int e = 0; e < EEXP; e++) red[tid][e] = acc[e];
    __syncthreads();
    for (int off = 128; off > 0; off >>= 1) {
        if (tid < off) {
#pragma unroll
            for (int e = 0; e < EEXP; e++) red[tid][e] += red[tid + off][e];
        }
        __syncthreads();
    }

    if (tid == 0) {
        float v[EEXP];
#pragma unroll
        for (int e = 0; e < EEXP; e++) v[e] = red[0][e];
        // stable top-2 (first index wins ties, matching jax top_k)
        int i1 = 0;
#pragma unroll
        for (int e = 1; e < EEXP; e++) if (v[e] > v[i1]) i1 = e;
        int i2 = -1;
#pragma unroll
        for (int e = 0; e < EEXP; e++) {
            if (e == i1) continue;
            if (i2 < 0 || v[e] > v[i2]) i2 = e;
        }
        float wa = 1.f / (1.f + expf(v[i2] - v[i1]));  // softmax of top-2
        g_te[2 * t]     = i1;
        g_te[2 * t + 1] = i2;
        g_tw[2 * t]     = wa;
        g_tw[2 * t + 1] = 1.f - wa;
        atomicAdd(&g_count[i1], 1);
        atomicAdd(&g_count[i2], 1);
    }
}

// Padded prefix sum (tiny).
__global__ void k_offs() {
    if (threadIdx.x == 0) {
        int o = 0;
#pragma unroll
        for (int e = 0; e < EEXP; e++) {
            g_offs[e] = o;
            o += (g_count[e] + SEGPAD - 1) & ~(SEGPAD - 1);
            g_cursor[e] = 0;
        }
        g_offs[EEXP] = o;
    }
}

// Gather: one warp per assignment copies the x row into its slot.
__global__ void k_gather(const float* __restrict__ x) {
    int a = blockIdx.x * 8 + (threadIdx.x >> 5);
    int lane = threadIdx.x & 31;
    if (a >= NASSIGN) return;
    int t = a >> 1;
    int e = g_te[a];
    int slot = 0;
    if (lane == 0) {
        slot = g_offs[e] + atomicAdd(&g_cursor[e], 1);
        g_slot[a] = slot;
    }
    slot = __shfl_sync(0xffffffffu, slot, 0);
    const float4* src = (const float4*)(x + (size_t)t * DDIM);
    float4* dst = (float4*)(g_xp + (size_t)slot * DDIM);
#pragma unroll
    for (int i = 0; i < 8; i++) dst[lane + 32 * i] = src[lane + 32 * i];
}

// Zero the pad rows of each expert segment so GEMMs are clean.
__global__ void k_zeropad() {
    int e = blockIdx.x;
    int start = g_offs[e] + g_count[e];
    int end = g_offs[e + 1];
    for (int r = start; r < end; r++) {
        float4* dst = (float4*)(g_xp + (size_t)r * DDIM);
        for (int i = threadIdx.x; i < DDIM / 4; i += 256)
            dst[i] = make_float4(0.f, 0.f, 0.f, 0.f);
    }
}

__device__ __forceinline__ float gelu_tanh(float v) {
    float v3 = v * v * v;
    return 0.5f * v * (1.f + tanhf(0.7978845608028654f * (v + 0.044715f * v3)));
}

// Tiled fp32 GEMM over padded expert segments.
// mode 0: C=g_h = gelu(g_xp @ w1[e])   K=DDIM, N=FDIM
// mode 1: C=g_y = g_h @ w2[e]          K=FDIM, N=DDIM
#define BM 128
#define BN 128
#define BK 8
__global__ __launch_bounds__(256, 2)
void k_gemm(const float* __restrict__ Wbase, int K, int N, int doGelu) {
    int row0 = blockIdx.x * BM;
    int total = g_offs[EEXP];
    if (row0 >= total) return;

    int e = 0;
    while (g_offs[e + 1] <= row0) e++;

    const float* A = doGelu ? g_xp : g_h;
    float* C       = doGelu ? g_h  : g_y;
    const float* B = Wbase + (size_t)e * K * N + blockIdx.y * BN;

    __shared__ float As[BK][BM];
    __shared__ float Bs[BK][BN];

    int tid = threadIdx.x;
    int aRow = tid >> 1, aCol = (tid & 1) * 4;     // 128x8 A tile
    int bRow = tid >> 5, bCol = (tid & 31) * 4;    // 8x128 B tile
    int tx = tid & 15, ty = tid >> 4;

    const float* Aptr = A + (size_t)(row0 + aRow) * K + aCol;
    const float* Bptr = B + (size_t)bRow * N + bCol;

    float acc[8][8];
#pragma unroll
    for (int i = 0; i < 8; i++)
#pragma unroll
        for (int j = 0; j < 8; j++) acc[i][j] = 0.f;

    for (int k0 = 0; k0 < K; k0 += BK) {
        float4 av = *(const float4*)(Aptr + k0);
        float4 bv = *(const float4*)(Bptr + (size_t)k0 * N);
        As[aCol + 0][aRow] = av.x;
        As[aCol + 1][aRow] = av.y;
        As[aCol + 2][aRow] = av.z;
        As[aCol + 3][aRow] = av.w;
        *(float4*)&Bs[bRow][bCol] = bv;
        __syncthreads();
#pragma unroll
        for (int kk = 0; kk < BK; kk++) {
            float a[8], b[8];
            *(float4*)(a)     = *(const float4*)&As[kk][ty * 8];
            *(float4*)(a + 4) = *(const float4*)&As[kk][ty * 8 + 4];
            *(float4*)(b)     = *(const float4*)&Bs[kk][tx * 8];
            *(float4*)(b + 4) = *(const float4*)&Bs[kk][tx * 8 + 4];
#pragma unroll
            for (int i = 0; i < 8; i++)
#pragma unroll
                for (int j = 0; j < 8; j++) acc[i][j] += a[i] * b[j];
        }
        __syncthreads();
    }

#pragma unroll
    for (int i = 0; i < 8; i++) {
        float* cp = C + (size_t)(row0 + ty * 8 + i) * N + blockIdx.y * BN + tx * 8;
#pragma unroll
        for (int j = 0; j < 8; j += 4) {
            float4 v;
            v.x = acc[i][j + 0]; v.y = acc[i][j + 1];
            v.z = acc[i][j + 2]; v.w = acc[i][j + 3];
            if (doGelu) {
                v.x = gelu_tanh(v.x); v.y = gelu_tanh(v.y);
                v.z = gelu_tanh(v.z); v.w = gelu_tanh(v.w);
            }
            *(float4*)(cp + j) = v;
        }
    }
}

// Combine: out[t] = w0*y[slot0] + w1*y[slot1]. One warp per token.
__global__ void k_combine(float* __restrict__ out) {
    int t = blockIdx.x * 8 + (threadIdx.x >> 5);
    int lane = threadIdx.x & 31;
    if (t >= T_TOK) return;
    int a0 = g_slot[2 * t], a1 = g_slot[2 * t + 1];
    float w0 = g_tw[2 * t], w1 = g_tw[2 * t + 1];
    const float4* y0 = (const float4*)(g_y + (size_t)a0 * DDIM);
    const float4* y1 = (const float4*)(g_y + (size_t)a1 * DDIM);
    float4* o = (float4*)(out + (size_t)t * DDIM);
#pragma unroll
    for (int i = 0; i < 8; i++) {
        int idx = lane + 32 * i;
        float4 p = y0[idx], q = y1[idx];
        o[idx] = make_float4(w0 * p.x + w1 * q.x, w0 * p.y + w1 * q.y,
                             w0 * p.z + w1 * q.z, w0 * p.w + w1 * q.w);
    }
}

// ---------------------------------------------------------------------------
extern "C" void kernel_launch(void* const* d_in, const int* in_sizes, int n_in,
                              void* d_out, int out_size) {
    const float* x  = (const float*)d_in[0];
    const float* Wg = (const float*)d_in[1];
    const float* w1 = (const float*)d_in[2];
    const float* w2 = (const float*)d_in[3];
    float* out = (float*)d_out;

    k_init<<<1, 32>>>();
    k_gate<<<T_TOK, 256>>>(x, Wg);
    k_offs<<<1, 32>>>();
    k_gather<<<NASSIGN / 8, 256>>>(x);
    k_zeropad<<<EEXP, 256>>>();

    dim3 grid1(MAXSLOTS / BM, FDIM / BN);   // (136, 32)
    k_gemm<<<grid1, 256>>>(w1, DDIM, FDIM, 1);

    dim3 grid2(MAXSLOTS / BM, DDIM / BN);   // (136, 8)
    k_gemm<<<grid2, 256>>>(w2, FDIM, DDIM, 0);

    k_combine<<<T_TOK / 8, 256>>>(out);
}

// round 3
// speedup vs baseline: 2.0970x; 2.0970x over previous
#include <cuda_runtime.h>
#include <cuda_bf16.h>
#include <cstdint>

// ---------------------------------------------------------------------------
// MoE layer: B=4,S=2048,D=1024,E=8,F=4096, top-k=2
// Round 3: mma.sync tf32 GEMMs (sm_80+ path; tcgen05 PTX rejected by this
// toolchain's compute_103 virtual target). cp.async double-buffered tiles.
// ---------------------------------------------------------------------------

#define T_TOK   8192
#define DDIM    1024
#define EEXP    8
#define FDIM    4096
#define NASSIGN (T_TOK * 2)
#define SEGPAD  128
#define MAXSLOTS (NASSIGN + EEXP * SEGPAD)  // 17408

__device__ float g_xp[MAXSLOTS * (size_t)DDIM];
__device__ float g_h [MAXSLOTS * (size_t)FDIM];
__device__ float g_y [MAXSLOTS * (size_t)DDIM];
__device__ float g_w1t[(size_t)EEXP * FDIM * DDIM];  // [e][f][d]
__device__ float g_w2t[(size_t)EEXP * DDIM * FDIM];  // [e][d][f]
__device__ int   g_te[NASSIGN];
__device__ float g_tw[NASSIGN];
__device__ int   g_slot[NASSIGN];
__device__ int   g_count[EEXP];
__device__ int   g_cursor[EEXP];
__device__ int   g_offs[EEXP + 1];

__device__ __forceinline__ float to_tf32(float v) {
    uint32_t u;
    asm("cvt.rna.tf32.f32 %0, %1;" : "=r"(u) : "f"(v));
    return __uint_as_float(u);
}
__device__ __forceinline__ uint32_t smem_u32(const void* p) {
    uint32_t a;
    asm("{ .reg .u64 t; cvta.to.shared.u64 t, %1; cvt.u32.u64 %0, t; }" : "=r"(a) : "l"(p));
    return a;
}
#define CP_ASYNC16(dst, src) \
    asm volatile("cp.async.cg.shared.global [%0], [%1], 16;" :: "r"(dst), "l"(src) : "memory")
#define CP_COMMIT() asm volatile("cp.async.commit_group;" ::: "memory")
#define CP_WAIT(n)  asm volatile("cp.async.wait_group %0;" :: "n"(n) : "memory")

__device__ __forceinline__ void mma_tf32(float* d, const uint32_t* a, const uint32_t* b) {
    asm volatile(
        "mma.sync.aligned.m16n8k8.row.col.f32.tf32.tf32.f32 "
        "{%0,%1,%2,%3}, {%4,%5,%6,%7}, {%8,%9}, {%0,%1,%2,%3};"
        : "+f"(d[0]), "+f"(d[1]), "+f"(d[2]), "+f"(d[3])
        : "r"(a[0]), "r"(a[1]), "r"(a[2]), "r"(a[3]), "r"(b[0]), "r"(b[1]));
}

// ---------------------------------------------------------------------------
__global__ void k_init() {
    int i = threadIdx.x;
    if (i < EEXP) { g_count[i] = 0; g_cursor[i] = 0; }
}

__global__ void k_gate(const float* __restrict__ x, const float* __restrict__ Wg) {
    int t = blockIdx.x;
    int tid = threadIdx.x;
    const float* xr = x + (size_t)t * DDIM;
    float acc[EEXP];
#pragma unroll
    for (int e = 0; e < EEXP; e++) acc[e] = 0.f;
    for (int d = tid; d < DDIM; d += 256) {
        float xv = xr[d];
        const float* wr = Wg + (size_t)d * EEXP;
#pragma unroll
        for (int e = 0; e < EEXP; e++) acc[e] += xv * wr[e];
    }
    __shared__ float red[256][EEXP];
#pragma unroll
    for (int e = 0; e < EEXP; e++) red[tid][e] = acc[e];
    __syncthreads();
    for (int off = 128; off > 0; off >>= 1) {
        if (tid < off) {
#pragma unroll
            for (int e = 0; e < EEXP; e++) red[tid][e] += red[tid + off][e];
        }
        __syncthreads();
    }
    if (tid == 0) {
        float v[EEXP];
#pragma unroll
        for (int e = 0; e < EEXP; e++) v[e] = red[0][e];
        int i1 = 0;
#pragma unroll
        for (int e = 1; e < EEXP; e++) if (v[e] > v[i1]) i1 = e;
        int i2 = -1;
#pragma unroll
        for (int e = 0; e < EEXP; e++) {
            if (e == i1) continue;
            if (i2 < 0 || v[e] > v[i2]) i2 = e;
        }
        float wa = 1.f / (1.f + expf(v[i2] - v[i1]));
        g_te[2 * t] = i1;  g_te[2 * t + 1] = i2;
        g_tw[2 * t] = wa;  g_tw[2 * t + 1] = 1.f - wa;
        atomicAdd(&g_count[i1], 1);
        atomicAdd(&g_count[i2], 1);
    }
}

__global__ void k_offs() {
    if (threadIdx.x == 0) {
        int o = 0;
#pragma unroll
        for (int e = 0; e < EEXP; e++) {
            g_offs[e] = o;
            o += (g_count[e] + SEGPAD - 1) & ~(SEGPAD - 1);
            g_cursor[e] = 0;
        }
        g_offs[EEXP] = o;
    }
}

// Gather + round to tf32 (RNA) so the MMA truncation is lossless.
__global__ void k_gather(const float* __restrict__ x) {
    int a = blockIdx.x * 8 + (threadIdx.x >> 5);
    int lane = threadIdx.x & 31;
    if (a >= NASSIGN) return;
    int t = a >> 1;
    int e = g_te[a];
    int slot = 0;
    if (lane == 0) {
        slot = g_offs[e] + atomicAdd(&g_cursor[e], 1);
        g_slot[a] = slot;
    }
    slot = __shfl_sync(0xffffffffu, slot, 0);
    const float4* src = (const float4*)(x + (size_t)t * DDIM);
    float4* dst = (float4*)(g_xp + (size_t)slot * DDIM);
#pragma unroll
    for (int i = 0; i < 8; i++) {
        float4 v = src[lane + 32 * i];
        v.x = to_tf32(v.x); v.y = to_tf32(v.y);
        v.z = to_tf32(v.z); v.w = to_tf32(v.w);
        dst[lane + 32 * i] = v;
    }
}

__global__ void k_zeropad() {
    int e = blockIdx.x;
    int start = g_offs[e] + g_count[e];
    int end = g_offs[e + 1];
    for (int r = start; r < end; r++) {
        float4* dst = (float4*)(g_xp + (size_t)r * DDIM);
        for (int i = threadIdx.x; i < DDIM / 4; i += 256)
            dst[i] = make_float4(0.f, 0.f, 0.f, 0.f);
    }
}

// Transpose per expert: in[e][R][C] -> out[e][C][R], rounding to tf32.
__global__ void k_transpose(const float* __restrict__ in, float* __restrict__ out,
                            int R, int C) {
    __shared__ float tile[32][33];
    const float* I = in + (size_t)blockIdx.z * R * C;
    float* O = out + (size_t)blockIdx.z * R * C;
    int c0 = blockIdx.x * 32, r0 = blockIdx.y * 32;
#pragma unroll
    for (int i = threadIdx.y; i < 32; i += 8)
        tile[i][threadIdx.x] = I[(size_t)(r0 + i) * C + c0 + threadIdx.x];
    __syncthreads();
#pragma unroll
    for (int i = threadIdx.y; i < 32; i += 8)
        O[(size_t)(c0 + i) * R + r0 + threadIdx.x] = to_tf32(tile[threadIdx.x][i]);
}

__device__ __forceinline__ float gelu_tanh(float v) {
    float v3 = v * v * v;
    return 0.5f * v * (1.f + tanhf(0.7978845608028654f * (v + 0.044715f * v3)));
}

// ---------------------------------------------------------------------------
// mma.sync tf32 GEMM: C[m][n] = A[m][k] * Bt[n][k] over padded expert segments.
// BM=128, BN=256, BK=32. 8 warps (2 m x 4 n), warp tile 64x64.
#define BM 128
#define BN 256
#define BKF 32
#define ASTRIDE 36
#define BSTRIDE 36
#define AS_ELEMS (BM * ASTRIDE)              // 4608
#define BS_ELEMS (BN * BSTRIDE)              // 9216
#define SMEM_GEMM ((2 * AS_ELEMS + 2 * BS_ELEMS) * 4)  // 110592

__global__ __launch_bounds__(256, 1)
void k_gemm_mma(const float* __restrict__ Wt, int K, int Ntot, int doGelu) {
    int row0 = blockIdx.x * BM;
    if (row0 >= g_offs[EEXP]) return;
    int e = 0;
    while (g_offs[e + 1] <= row0) e++;

    extern __shared__ float smem[];
    float* As = smem;                 // [2][BM][ASTRIDE]
    float* Bs = smem + 2 * AS_ELEMS;  // [2][BN][BSTRIDE]

    int tid = threadIdx.x, wid = tid >> 5, lane = tid & 31;
    int gid = lane >> 2, tig = lane & 3;
    int warp_m = wid & 1, warp_n = wid >> 1;

    const float* A = doGelu ? g_xp : g_h;
    float* C       = doGelu ? g_h  : g_y;
    const float* B = Wt + ((size_t)e * Ntot + (size_t)blockIdx.y * BN) * K;

    // loader: 8 threads per row, 16B each; A: 4 passes of 32 rows, B: 8 passes.
    int lrow = tid >> 3, lcol = (tid & 7) * 4;
    const float* asrc = A + (size_t)(row0 + lrow) * K + lcol;
    const float* bsrc = B + (size_t)lrow * K + lcol;
    uint32_t sbase = smem_u32(smem);

    float acc[4][8][4];
#pragma unroll
    for (int mt = 0; mt < 4; mt++)
#pragma unroll
        for (int nt = 0; nt < 8; nt++)
#pragma unroll
            for (int j = 0; j < 4; j++) acc[mt][nt][j] = 0.f;

    int KT = K / BKF;

    // prologue: load tile 0
    {
        uint32_t ad = sbase + ((uint32_t)lrow * ASTRIDE + lcol) * 4;
        uint32_t bd = sbase + (2u * AS_ELEMS + (uint32_t)lrow * BSTRIDE + lcol) * 4;
#pragma unroll
        for (int p = 0; p < 4; p++)
            CP_ASYNC16(ad + p * 32 * ASTRIDE * 4, asrc + (size_t)p * 32 * K);
#pragma unroll
        for (int p = 0; p < 8; p++)
            CP_ASYNC16(bd + p * 32 * BSTRIDE * 4, bsrc + (size_t)p * 32 * K);
        CP_COMMIT();
    }

    for (int kt = 0; kt < KT; kt++) {
        int buf = kt & 1;
        if (kt + 1 < KT) {
            int nbuf = buf ^ 1;
            int k0 = (kt + 1) * BKF;
            uint32_t ad = sbase + ((uint32_t)nbuf * AS_ELEMS + (uint32_t)lrow * ASTRIDE + lcol) * 4;
            uint32_t bd = sbase + (2u * AS_ELEMS + (uint32_t)nbuf * BS_ELEMS + (uint32_t)lrow * BSTRIDE + lcol) * 4;
#pragma unroll
            for (int p = 0; p < 4; p++)
                CP_ASYNC16(ad + p * 32 * ASTRIDE * 4, asrc + k0 + (size_t)p * 32 * K);
#pragma unroll
            for (int p = 0; p < 8; p++)
                CP_ASYNC16(bd + p * 32 * BSTRIDE * 4, bsrc + k0 + (size_t)p * 32 * K);
            CP_COMMIT();
            CP_WAIT(1);
        } else {
            CP_WAIT(0);
        }
        __syncthreads();

        const float* at = As + buf * AS_ELEMS + (warp_m * 64 + gid) * ASTRIDE;
        const float* bt = Bs + buf * BS_ELEMS + (warp_n * 64 + gid) * BSTRIDE;
#pragma unroll
        for (int ks = 0; ks < 4; ks++) {
            int k0 = ks * 8;
            uint32_t afrag[4][4];
#pragma unroll
            for (int mt = 0; mt < 4; mt++) {
                const float* ap = at + mt * 16 * ASTRIDE + k0 + tig;
                afrag[mt][0] = __float_as_uint(ap[0]);
                afrag[mt][1] = __float_as_uint(ap[8 * ASTRIDE]);
                afrag[mt][2] = __float_as_uint(ap[4]);
                afrag[mt][3] = __float_as_uint(ap[8 * ASTRIDE + 4]);
            }
            uint32_t bfrag[8][2];
#pragma unroll
            for (int nt = 0; nt < 8; nt++) {
                const float* bp = bt + nt * 8 * BSTRIDE + k0 + tig;
                bfrag[nt][0] = __float_as_uint(bp[0]);
                bfrag[nt][1] = __float_as_uint(bp[4]);
            }
#pragma unroll
            for (int mt = 0; mt < 4; mt++)
#pragma unroll
                for (int nt = 0; nt < 8; nt++)
                    mma_tf32(acc[mt][nt], afrag[mt], bfrag[nt]);
        }
        __syncthreads();
    }

    // epilogue
#pragma unroll
    for (int mt = 0; mt < 4; mt++) {
        int mrow = row0 + warp_m * 64 + mt * 16 + gid;
#pragma unroll
        for (int nt = 0; nt < 8; nt++) {
            int col = blockIdx.y * BN + warp_n * 64 + nt * 8 + 2 * tig;
            float2 v0 = make_float2(acc[mt][nt][0], acc[mt][nt][1]);
            float2 v1 = make_float2(acc[mt][nt][2], acc[mt][nt][3]);
            if (doGelu) {
                v0.x = to_tf32(gelu_tanh(v0.x)); v0.y = to_tf32(gelu_tanh(v0.y));
                v1.x = to_tf32(gelu_tanh(v1.x)); v1.y = to_tf32(gelu_tanh(v1.y));
            }
            *(float2*)(C + (size_t)mrow * Ntot + col) = v0;
            *(float2*)(C + (size_t)(mrow + 8) * Ntot + col) = v1;
        }
    }
}

__global__ void k_combine(float* __restrict__ out) {
    int t = blockIdx.x * 8 + (threadIdx.x >> 5);
    int lane = threadIdx.x & 31;
    if (t >= T_TOK) return;
    int a0 = g_slot[2 * t], a1 = g_slot[2 * t + 1];
    float w0 = g_tw[2 * t], w1 = g_tw[2 * t + 1];
    const float4* y0 = (const float4*)(g_y + (size_t)a0 * DDIM);
    const float4* y1 = (const float4*)(g_y + (size_t)a1 * DDIM);
    float4* o = (float4*)(out + (size_t)t * DDIM);
#pragma unroll
    for (int i = 0; i < 8; i++) {
        int idx = lane + 32 * i;
        float4 p = y0[idx], q = y1[idx];
        o[idx] = make_float4(w0 * p.x + w1 * q.x, w0 * p.y + w1 * q.y,
                             w0 * p.z + w1 * q.z, w0 * p.w + w1 * q.w);
    }
}

// ---------------------------------------------------------------------------
extern "C" void kernel_launch(void* const* d_in, const int* in_sizes, int n_in,
                              void* d_out, int out_size) {
    const float* x  = (const float*)d_in[0];
    const float* Wg = (const float*)d_in[1];
    const float* w1 = (const float*)d_in[2];
    const float* w2 = (const float*)d_in[3];
    float* out = (float*)d_out;

    cudaFuncSetAttribute(k_gemm_mma, cudaFuncAttributeMaxDynamicSharedMemorySize, SMEM_GEMM);

    float* w1t; cudaGetSymbolAddress((void**)&w1t, g_w1t);
    float* w2t; cudaGetSymbolAddress((void**)&w2t, g_w2t);

    k_init<<<1, 32>>>();
    k_gate<<<T_TOK, 256>>>(x, Wg);
    k_offs<<<1, 32>>>();
    k_gather<<<NASSIGN / 8, 256>>>(x);
    k_zeropad<<<EEXP, 256>>>();

    dim3 tb(32, 8);
    // w1[e]: [D][F] -> w1t[e]: [F][D]
    k_transpose<<<dim3(FDIM / 32, DDIM / 32, EEXP), tb>>>(w1, w1t, DDIM, FDIM);
    // w2[e]: [F][D] -> w2t[e]: [D][F]
    k_transpose<<<dim3(DDIM / 32, FDIM / 32, EEXP), tb>>>(w2, w2t, FDIM, DDIM);

    dim3 grid1(MAXSLOTS / BM, FDIM / BN);   // (136, 16)
    k_gemm_mma<<<grid1, 256, SMEM_GEMM>>>(w1t, DDIM, FDIM, 1);

    dim3 grid2(MAXSLOTS / BM, DDIM / BN);   // (136, 4)
    k_gemm_mma<<<grid2, 256, SMEM_GEMM>>>(w2t, FDIM, DDIM, 0);

    k_combine<<<T_TOK / 8, 256>>>(out);
}

// round 4
// speedup vs baseline: 3.6512x; 1.7412x over previous
#include <cuda_runtime.h>
#include <cuda_bf16.h>
#include <cstdint>

// ---------------------------------------------------------------------------
// MoE layer: B=4,S=2048,D=1024,E=8,F=4096, top-k=2
// Round 4: mma.sync tf32, 512-thread CTAs (4 warps/SMSP), direct [k][n] B
// staging (no weight transposes, inline cvt.rna on B fragments), 3-stage
// cp.async pipeline, warp-per-token gate.
// ---------------------------------------------------------------------------

#define T_TOK   8192
#define DDIM    1024
#define EEXP    8
#define FDIM    4096
#define NASSIGN (T_TOK * 2)
#define SEGPAD  128
#define MAXSLOTS (NASSIGN + EEXP * SEGPAD)  // 17408

__device__ float g_xp[MAXSLOTS * (size_t)DDIM];
__device__ float g_h [MAXSLOTS * (size_t)FDIM];
__device__ float g_y [MAXSLOTS * (size_t)DDIM];
__device__ int   g_te[NASSIGN];
__device__ float g_tw[NASSIGN];
__device__ int   g_slot[NASSIGN];
__device__ int   g_count[EEXP];
__device__ int   g_cursor[EEXP];
__device__ int   g_offs[EEXP + 1];

__device__ __forceinline__ float to_tf32(float v) {
    uint32_t u;
    asm("cvt.rna.tf32.f32 %0, %1;" : "=r"(u) : "f"(v));
    return __uint_as_float(u);
}
__device__ __forceinline__ uint32_t cvt_tf32_u(uint32_t v) {
    uint32_t u;
    asm("cvt.rna.tf32.f32 %0, %1;" : "=r"(u) : "r"(v));
    return u;
}
__device__ __forceinline__ uint32_t smem_u32(const void* p) {
    uint32_t a;
    asm("{ .reg .u64 t; cvta.to.shared.u64 t, %1; cvt.u32.u64 %0, t; }" : "=r"(a) : "l"(p));
    return a;
}
#define CP_ASYNC16(dst, src) \
    asm volatile("cp.async.cg.shared.global [%0], [%1], 16;" :: "r"(dst), "l"(src) : "memory")
#define CP_COMMIT() asm volatile("cp.async.commit_group;" ::: "memory")
#define CP_WAIT(n)  asm volatile("cp.async.wait_group %0;" :: "n"(n) : "memory")

__device__ __forceinline__ void mma_tf32(float* d, const uint32_t* a, const uint32_t* b) {
    asm volatile(
        "mma.sync.aligned.m16n8k8.row.col.f32.tf32.tf32.f32 "
        "{%0,%1,%2,%3}, {%4,%5,%6,%7}, {%8,%9}, {%0,%1,%2,%3};"
        : "+f"(d[0]), "+f"(d[1]), "+f"(d[2]), "+f"(d[3])
        : "r"(a[0]), "r"(a[1]), "r"(a[2]), "r"(a[3]), "r"(b[0]), "r"(b[1]));
}

// ---------------------------------------------------------------------------
__global__ void k_init() {
    int i = threadIdx.x;
    if (i < EEXP) { g_count[i] = 0; g_cursor[i] = 0; }
}

// Gate: one warp per token.
__global__ void k_gate(const float* __restrict__ x, const float* __restrict__ Wg) {
    int t = blockIdx.x * 8 + (threadIdx.x >> 5);
    int lane = threadIdx.x & 31;
    const float* xr = x + (size_t)t * DDIM;

    float acc[EEXP];
#pragma unroll
    for (int e = 0; e < EEXP; e++) acc[e] = 0.f;
#pragma unroll 4
    for (int i = 0; i < DDIM / 32; i++) {
        int d = i * 32 + lane;
        float xv = xr[d];
        const float4* wr = (const float4*)(Wg + (size_t)d * EEXP);
        float4 w0 = wr[0], w1 = wr[1];
        acc[0] += xv * w0.x; acc[1] += xv * w0.y;
        acc[2] += xv * w0.z; acc[3] += xv * w0.w;
        acc[4] += xv * w1.x; acc[5] += xv * w1.y;
        acc[6] += xv * w1.z; acc[7] += xv * w1.w;
    }
#pragma unroll
    for (int off = 16; off > 0; off >>= 1)
#pragma unroll
        for (int e = 0; e < EEXP; e++)
            acc[e] += __shfl_xor_sync(0xffffffffu, acc[e], off);

    if (lane == 0) {
        int i1 = 0;
#pragma unroll
        for (int e = 1; e < EEXP; e++) if (acc[e] > acc[i1]) i1 = e;
        int i2 = -1;
#pragma unroll
        for (int e = 0; e < EEXP; e++) {
            if (e == i1) continue;
            if (i2 < 0 || acc[e] > acc[i2]) i2 = e;
        }
        float wa = 1.f / (1.f + expf(acc[i2] - acc[i1]));
        g_te[2 * t] = i1;  g_te[2 * t + 1] = i2;
        g_tw[2 * t] = wa;  g_tw[2 * t + 1] = 1.f - wa;
        atomicAdd(&g_count[i1], 1);
        atomicAdd(&g_count[i2], 1);
    }
}

__global__ void k_offs() {
    if (threadIdx.x == 0) {
        int o = 0;
#pragma unroll
        for (int e = 0; e < EEXP; e++) {
            g_offs[e] = o;
            o += (g_count[e] + SEGPAD - 1) & ~(SEGPAD - 1);
            g_cursor[e] = 0;
        }
        g_offs[EEXP] = o;
    }
}

// Gather + round to tf32 (RNA) so the MMA truncation is lossless.
__global__ void k_gather(const float* __restrict__ x) {
    int a = blockIdx.x * 8 + (threadIdx.x >> 5);
    int lane = threadIdx.x & 31;
    if (a >= NASSIGN) return;
    int t = a >> 1;
    int e = g_te[a];
    int slot = 0;
    if (lane == 0) {
        slot = g_offs[e] + atomicAdd(&g_cursor[e], 1);
        g_slot[a] = slot;
    }
    slot = __shfl_sync(0xffffffffu, slot, 0);
    const float4* src = (const float4*)(x + (size_t)t * DDIM);
    float4* dst = (float4*)(g_xp + (size_t)slot * DDIM);
#pragma unroll
    for (int i = 0; i < 8; i++) {
        float4 v = src[lane + 32 * i];
        v.x = to_tf32(v.x); v.y = to_tf32(v.y);
        v.z = to_tf32(v.z); v.w = to_tf32(v.w);
        dst[lane + 32 * i] = v;
    }
}

__global__ void k_zeropad() {
    int e = blockIdx.x;
    int start = g_offs[e] + g_count[e];
    int end = g_offs[e + 1];
    for (int r = start; r < end; r++) {
        float4* dst = (float4*)(g_xp + (size_t)r * DDIM);
        for (int i = threadIdx.x; i < DDIM / 4; i += 256)
            dst[i] = make_float4(0.f, 0.f, 0.f, 0.f);
    }
}

__device__ __forceinline__ float gelu_tanh(float v) {
    float v3 = v * v * v;
    return 0.5f * v * (1.f + tanhf(0.7978845608028654f * (v + 0.044715f * v3)));
}

// ---------------------------------------------------------------------------
// mma.sync tf32 GEMM: C[m][n] = A[m][k] * W[e][k][n] over padded segments.
// BM=128, BN=256, BK=32, 512 threads (16 warps, warp tile 64x32), 3 stages.
// A smem: [m][k] stride 36; B smem: [k][n] stride 264 (both conflict-free).
#define BM 128
#define BN 256
#define BKF 32
#define NSTAGE 3
#define ASTRIDE 36
#define BSTRIDE 264
#define AS_ELEMS (BM * ASTRIDE)    // 4608
#define BS_ELEMS (BKF * BSTRIDE)   // 8448
#define SMEM_GEMM (NSTAGE * (AS_ELEMS + BS_ELEMS) * 4)  // 156672

__global__ __launch_bounds__(512, 1)
void k_gemm_mma(const float* __restrict__ W, int K, int Ntot, int doGelu) {
    int row0 = blockIdx.x * BM;
    if (row0 >= g_offs[EEXP]) return;
    int e = 0;
    while (g_offs[e + 1] <= row0) e++;

    extern __shared__ float smem[];
    float* As = smem;                      // [NSTAGE][BM][ASTRIDE]
    float* Bs = smem + NSTAGE * AS_ELEMS;  // [NSTAGE][BKF][BSTRIDE]

    int tid = threadIdx.x, wid = tid >> 5, lane = tid & 31;
    int gid = lane >> 2, tig = lane & 3;
    int warp_m = wid & 1, warp_n = wid >> 1;   // 2 x 8 warps, tile 64x32

    const float* A = doGelu ? g_xp : g_h;
    float* C       = doGelu ? g_h  : g_y;
    const float* B = W + (size_t)e * K * Ntot + (size_t)blockIdx.y * BN;

    // Loaders. A: 128x32 floats = 1024 16B-chunks, 2/thread.
    int arow0 = tid >> 2, acol0 = (tid & 3) * 8;   // 2 chunks: acol0, acol0+4... no:
    // chunks c = tid, tid+512 -> row=c>>3, col=(c&7)*4 : rows tid>>3 and tid>>3+64
    int ar = tid >> 3, ac = (tid & 7) * 4;
    // B: 32x256 floats = 2048 chunks, 4/thread: c = tid + i*512 -> row=c>>6, col=(c&63)*4
    int br = tid >> 6, bc = (tid & 63) * 4;
    (void)arow0; (void)acol0;

    const float* asrc0 = A + (size_t)(row0 + ar) * K + ac;
    const float* asrc1 = A + (size_t)(row0 + ar + 64) * K + ac;
    const float* bsrc0 = B + (size_t)br * Ntot + bc;

    uint32_t sbase = smem_u32(smem);
    uint32_t a_d0 = sbase + ((uint32_t)ar * ASTRIDE + ac) * 4;
    uint32_t a_d1 = a_d0 + 64u * ASTRIDE * 4;
    uint32_t b_d0 = sbase + (uint32_t)NSTAGE * AS_ELEMS * 4 + ((uint32_t)br * BSTRIDE + bc) * 4;

    float acc[4][4][4];
#pragma unroll
    for (int mt = 0; mt < 4; mt++)
#pragma unroll
        for (int nt = 0; nt < 4; nt++)
#pragma unroll
            for (int j = 0; j < 4; j++) acc[mt][nt][j] = 0.f;

    int KT = K / BKF;

#define LOAD_TILE(kt, st) do { \
    int _k0 = (kt) * BKF; \
    uint32_t _ao = (uint32_t)(st) * AS_ELEMS * 4; \
    uint32_t _bo = (uint32_t)(st) * BS_ELEMS * 4; \
    CP_ASYNC16(a_d0 + _ao, asrc0 + _k0); \
    CP_ASYNC16(a_d1 + _ao, asrc1 + _k0); \
    CP_ASYNC16(b_d0 + _bo,                      bsrc0 + (size_t)_k0 * Ntot); \
    CP_ASYNC16(b_d0 + _bo +  8u * BSTRIDE * 4,  bsrc0 + (size_t)(_k0 + 8)  * Ntot); \
    CP_ASYNC16(b_d0 + _bo + 16u * BSTRIDE * 4,  bsrc0 + (size_t)(_k0 + 16) * Ntot); \
    CP_ASYNC16(b_d0 + _bo + 24u * BSTRIDE * 4,  bsrc0 + (size_t)(_k0 + 24) * Ntot); \
} while (0)

    // prologue: stages 0,1
    LOAD_TILE(0, 0); CP_COMMIT();
    if (KT > 1) LOAD_TILE(1, 1);
    CP_COMMIT();

    int stage = 0;
    for (int kt = 0; kt < KT; kt++) {
        CP_WAIT(1);
        __syncthreads();
        // issue tile kt+2 into the stage freed at iter kt-1; commit every iter
        int nkt = kt + 2;
        int nst = stage + 2; if (nst >= NSTAGE) nst -= NSTAGE;
        if (nkt < KT) LOAD_TILE(nkt, nst);
        CP_COMMIT();

        const float* at = As + stage * AS_ELEMS + (warp_m * 64 + gid) * ASTRIDE;
        const float* bt = Bs + stage * BS_ELEMS + tig * BSTRIDE + warp_n * 32 + gid;
#pragma unroll
        for (int ks = 0; ks < 4; ks++) {
            int k0 = ks * 8;
            uint32_t afrag[4][4];
#pragma unroll
            for (int mt = 0; mt < 4; mt++) {
                const float* ap = at + mt * 16 * ASTRIDE + k0 + tig;
                afrag[mt][0] = __float_as_uint(ap[0]);
                afrag[mt][1] = __float_as_uint(ap[8 * ASTRIDE]);
                afrag[mt][2] = __float_as_uint(ap[4]);
                afrag[mt][3] = __float_as_uint(ap[8 * ASTRIDE + 4]);
            }
            uint32_t bfrag[4][2];
#pragma unroll
            for (int nt = 0; nt < 4; nt++) {
                const float* bp = bt + (size_t)k0 * BSTRIDE + nt * 8;
                bfrag[nt][0] = cvt_tf32_u(__float_as_uint(bp[0]));
                bfrag[nt][1] = cvt_tf32_u(__float_as_uint(bp[4 * BSTRIDE]));
            }
#pragma unroll
            for (int mt = 0; mt < 4; mt++)
#pragma unroll
                for (int nt = 0; nt < 4; nt++)
                    mma_tf32(acc[mt][nt], afrag[mt], bfrag[nt]);
        }
        stage++; if (stage >= NSTAGE) stage = 0;
    }

    // epilogue
#pragma unroll
    for (int mt = 0; mt < 4; mt++) {
        int mrow = row0 + warp_m * 64 + mt * 16 + gid;
#pragma unroll
        for (int nt = 0; nt < 4; nt++) {
            int col = blockIdx.y * BN + warp_n * 32 + nt * 8 + 2 * tig;
            float2 v0 = make_float2(acc[mt][nt][0], acc[mt][nt][1]);
            float2 v1 = make_float2(acc[mt][nt][2], acc[mt][nt][3]);
            if (doGelu) {
                v0.x = to_tf32(gelu_tanh(v0.x)); v0.y = to_tf32(gelu_tanh(v0.y));
                v1.x = to_tf32(gelu_tanh(v1.x)); v1.y = to_tf32(gelu_tanh(v1.y));
            }
            *(float2*)(C + (size_t)mrow * Ntot + col) = v0;
            *(float2*)(C + (size_t)(mrow + 8) * Ntot + col) = v1;
        }
    }
}

__global__ void k_combine(float* __restrict__ out) {
    int t = blockIdx.x * 8 + (threadIdx.x >> 5);
    int lane = threadIdx.x & 31;
    if (t >= T_TOK) return;
    int a0 = g_slot[2 * t], a1 = g_slot[2 * t + 1];
    float w0 = g_tw[2 * t], w1 = g_tw[2 * t + 1];
    const float4* y0 = (const float4*)(g_y + (size_t)a0 * DDIM);
    const float4* y1 = (const float4*)(g_y + (size_t)a1 * DDIM);
    float4* o = (float4*)(out + (size_t)t * DDIM);
#pragma unroll
    for (int i = 0; i < 8; i++) {
        int idx = lane + 32 * i;
        float4 p = y0[idx], q = y1[idx];
        o[idx] = make_float4(w0 * p.x + w1 * q.x, w0 * p.y + w1 * q.y,
                             w0 * p.z + w1 * q.z, w0 * p.w + w1 * q.w);
    }
}

// ---------------------------------------------------------------------------
extern "C" void kernel_launch(void* const* d_in, const int* in_sizes, int n_in,
                              void* d_out, int out_size) {
    const float* x  = (const float*)d_in[0];
    const float* Wg = (const float*)d_in[1];
    const float* w1 = (const float*)d_in[2];
    const float* w2 = (const float*)d_in[3];
    float* out = (float*)d_out;

    cudaFuncSetAttribute(k_gemm_mma, cudaFuncAttributeMaxDynamicSharedMemorySize, SMEM_GEMM);

    k_init<<<1, 32>>>();
    k_gate<<<T_TOK / 8, 256>>>(x, Wg);
    k_offs<<<1, 32>>>();
    k_gather<<<NASSIGN / 8, 256>>>(x);
    k_zeropad<<<EEXP, 256>>>();

    dim3 grid1(MAXSLOTS / BM, FDIM / BN);   // (136, 16)
    k_gemm_mma<<<grid1, 512, SMEM_GEMM>>>(w1, DDIM, FDIM, 1);

    dim3 grid2(MAXSLOTS / BM, DDIM / BN);   // (136, 4)
    k_gemm_mma<<<grid2, 512, SMEM_GEMM>>>(w2, FDIM, DDIM, 0);

    k_combine<<<T_TOK / 8, 256>>>(out);
}